// round 7
// baseline (speedup 1.0000x reference)
#include <cuda_runtime.h>
#include <cuda_bf16.h>
#include <cstdint>

// Problem constants (fixed by the dataset): input [B, C, T] fp32
#define B_DIM 16
#define C_DIM 256
#define T_DIM 16000
#define EPS 1e-8f

#define TPB 256
#define T_PER_BLK 1024                 // 256 threads x 4 t (float4)
#define NCHUNK ((T_DIM + T_PER_BLK - 1) / T_PER_BLK)   // 16
#define C_SPLIT 8                      // K1: channel splits
#define CPS (C_DIM / C_SPLIT)          // 32 channels per split
#define C_GRP 4                        // K3: channels per block
#define NCGRP (C_DIM / C_GRP)          // 64

// scratch (device globals; allocation is forbidden)
__device__ float2 g_part [C_SPLIT * B_DIM * T_DIM];  // partial (sum,sumsq)  16 MB
__device__ float2 g_stats[B_DIM * T_DIM];            // (mean, inv_std)       2 MB

// ---------------- K1: partial channel reduction (pure streaming) ----------------
__global__ __launch_bounds__(TPB) void colsum_kernel(const float* __restrict__ x)
{
    const int cs = blockIdx.y;          // channel split 0..7
    const int b  = blockIdx.z;
    const int t4 = blockIdx.x * T_PER_BLK + threadIdx.x * 4;
    if (t4 >= T_DIM) return;            // 640 % 4 == 0: thread fully valid or not

    const float* px = x + ((size_t)b * C_DIM + cs * CPS) * T_DIM + t4;

    float4 s = make_float4(0.f, 0.f, 0.f, 0.f);
    float4 p = make_float4(0.f, 0.f, 0.f, 0.f);
    #pragma unroll 8
    for (int c = 0; c < CPS; c++) {
        const float4 v = __ldcs((const float4*)(px + (size_t)c * T_DIM));
        s.x += v.x; s.y += v.y; s.z += v.z; s.w += v.w;
        p.x = fmaf(v.x, v.x, p.x); p.y = fmaf(v.y, v.y, p.y);
        p.z = fmaf(v.z, v.z, p.z); p.w = fmaf(v.w, v.w, p.w);
    }

    float2* dst = g_part + ((size_t)cs * B_DIM + b) * T_DIM + t4;
    ((float4*)dst)[0] = make_float4(s.x, p.x, s.y, p.y);
    ((float4*)dst)[1] = make_float4(s.z, p.z, s.w, p.w);
}

// ---------------- K2: combine partials + per-batch scan -> (mean, inv_std) ----------------
#define SCAN_TPB 1024
#define EPT 16                                        // 1024*16 >= 16000

__global__ __launch_bounds__(SCAN_TPB) void scan_kernel()
{
    __shared__ float swS[32], swP[32];

    const int b    = blockIdx.x;
    const int tid  = threadIdx.x;
    const int lane = tid & 31;
    const int wid  = tid >> 5;
    const int start = tid * EPT;

    float vs[EPT], vp[EPT];
    #pragma unroll
    for (int j = 0; j < EPT; j++) {
        const int i = start + j;
        float S = 0.f, P = 0.f;
        if (i < T_DIM) {
            #pragma unroll
            for (int cs = 0; cs < C_SPLIT; cs++) {
                float2 v = g_part[((size_t)cs * B_DIM + b) * T_DIM + i];
                S += v.x; P += v.y;
            }
        }
        vs[j] = S; vp[j] = P;
    }
    #pragma unroll
    for (int j = 1; j < EPT; j++) { vs[j] += vs[j - 1]; vp[j] += vp[j - 1]; }

    // block-exclusive prefix of thread totals
    float tS = vs[EPT - 1], tP = vp[EPT - 1];
    float iS = tS, iP = tP;
    #pragma unroll
    for (int off = 1; off < 32; off <<= 1) {
        float nS = __shfl_up_sync(0xffffffffu, iS, off);
        float nP = __shfl_up_sync(0xffffffffu, iP, off);
        if (lane >= off) { iS += nS; iP += nP; }
    }
    if (lane == 31) { swS[wid] = iS; swP[wid] = iP; }
    __syncthreads();
    if (wid == 0) {
        float wS = swS[lane], wP = swP[lane];
        #pragma unroll
        for (int off = 1; off < 32; off <<= 1) {
            float nS = __shfl_up_sync(0xffffffffu, wS, off);
            float nP = __shfl_up_sync(0xffffffffu, wP, off);
            if (lane >= off) { wS += nS; wP += nP; }
        }
        swS[lane] = wS - swS[lane];               // exclusive warp offset
        swP[lane] = wP - swP[lane];
    }
    __syncthreads();
    const float excS = swS[wid] + (iS - tS);
    const float excP = swP[wid] + (iP - tP);

    const size_t base = (size_t)b * T_DIM;
    #pragma unroll
    for (int j = 0; j < EPT; j++) {
        const int i = start + j;
        if (i < T_DIM) {
            const float cumS = excS + vs[j];
            const float cumP = excP + vp[j];
            const float cnt  = (float)(i + 1) * (float)C_DIM;
            const float mean = cumS / cnt;
            const float inv  = rsqrtf(cumP / cnt - mean * mean + EPS);
            g_stats[base + i] = make_float2(mean, inv);
        }
    }
}

// ---------------- K3: normalize, 4 channels/block (stats reused in regs) ----------------
__global__ __launch_bounds__(TPB) void norm_kernel(
    const float* __restrict__ x,
    const float* __restrict__ gain,
    const float* __restrict__ bias,
    float* __restrict__ out)
{
    const int cg = blockIdx.y;          // channel group 0..63
    const int b  = blockIdx.z;
    const int t4 = blockIdx.x * T_PER_BLK + threadIdx.x * 4;
    if (t4 >= T_DIM) return;

    const float4* sp = (const float4*)(g_stats + (size_t)b * T_DIM + t4);
    const float4 s01 = sp[0];           // {mean0, inv0, mean1, inv1}
    const float4 s23 = sp[1];

    const int c0 = cg * C_GRP;
    const size_t base = ((size_t)b * C_DIM + c0) * T_DIM + t4;

    // 4 independent load streams -> high MLP
    float4 v[C_GRP];
    #pragma unroll
    for (int j = 0; j < C_GRP; j++)
        v[j] = __ldcs((const float4*)(x + base + (size_t)j * T_DIM));

    #pragma unroll
    for (int j = 0; j < C_GRP; j++) {
        const float g  = __ldg(gain + c0 + j);
        const float bi = __ldg(bias + c0 + j);
        float4 o;
        o.x = fmaf((v[j].x - s01.x) * s01.y, g, bi);
        o.y = fmaf((v[j].y - s01.z) * s01.w, g, bi);
        o.z = fmaf((v[j].z - s23.x) * s23.y, g, bi);
        o.w = fmaf((v[j].w - s23.z) * s23.w, g, bi);
        __stcs((float4*)(out + base + (size_t)j * T_DIM), o);
    }
}

extern "C" void kernel_launch(void* const* d_in, const int* in_sizes, int n_in,
                              void* d_out, int out_size)
{
    const float* x    = (const float*)d_in[0];
    const float* gain = (const float*)d_in[1];
    const float* bias = (const float*)d_in[2];
    float* out = (float*)d_out;

    colsum_kernel<<<dim3(NCHUNK, C_SPLIT, B_DIM), TPB>>>(x);
    scan_kernel  <<<B_DIM, SCAN_TPB>>>();
    norm_kernel  <<<dim3(NCHUNK, NCGRP, B_DIM), TPB>>>(x, gain, bias, out);
}

// round 8
// speedup vs baseline: 1.3548x; 1.3548x over previous
#include <cuda_runtime.h>
#include <cuda_bf16.h>
#include <cstdint>

// Problem constants (fixed by the dataset): input [B, C, T] fp32
#define B_DIM 16
#define C_DIM 256
#define T_DIM 16000
#define EPS 1e-8f

#define TPB 256
#define T_PER_BLK 1024                 // 256 threads x 4 t (float4)
#define NCHUNK ((T_DIM + T_PER_BLK - 1) / T_PER_BLK)   // 16
#define C_SPLIT 8                      // K1: channel splits
#define CPS (C_DIM / C_SPLIT)          // 32 channels per split

#define K3_CSPLIT 4                    // K3: channel slices per (b, chunk)
#define K3_CPS (C_DIM / K3_CSPLIT)     // 64 channels per block

// scratch (device globals; allocation is forbidden)
__device__ float2 g_part  [C_SPLIT * B_DIM * T_DIM]; // partial (sum,sumsq)  16 MB
__device__ float2 g_colsum[B_DIM * T_DIM];           // combined             2 MB
__device__ float2 g_stats [B_DIM * T_DIM];           // (mean, inv_std)      2 MB

// ---------------- K1: partial channel reduction (pure streaming) ----------------
__global__ __launch_bounds__(TPB) void colsum_kernel(const float* __restrict__ x)
{
    const int cs = blockIdx.y;          // channel split 0..7
    const int b  = blockIdx.z;
    const int t4 = blockIdx.x * T_PER_BLK + threadIdx.x * 4;
    if (t4 >= T_DIM) return;            // 640 % 4 == 0: thread fully valid or not

    const float* px = x + ((size_t)b * C_DIM + cs * CPS) * T_DIM + t4;

    float4 s = make_float4(0.f, 0.f, 0.f, 0.f);
    float4 p = make_float4(0.f, 0.f, 0.f, 0.f);
    #pragma unroll 8
    for (int c = 0; c < CPS; c++) {
        const float4 v = __ldcs((const float4*)(px + (size_t)c * T_DIM));
        s.x += v.x; s.y += v.y; s.z += v.z; s.w += v.w;
        p.x = fmaf(v.x, v.x, p.x); p.y = fmaf(v.y, v.y, p.y);
        p.z = fmaf(v.z, v.z, p.z); p.w = fmaf(v.w, v.w, p.w);
    }

    float2* dst = g_part + ((size_t)cs * B_DIM + b) * T_DIM + t4;
    ((float4*)dst)[0] = make_float4(s.x, p.x, s.y, p.y);
    ((float4*)dst)[1] = make_float4(s.z, p.z, s.w, p.w);
}

// ---------------- K2a: combine 8 partials -> g_colsum (parallel) ----------------
__global__ __launch_bounds__(TPB) void combine_kernel()
{
    // thread handles 2 consecutive (b,t) float2 pairs = one float4
    const int i2 = blockIdx.x * TPB + threadIdx.x;     // pair index
    if (i2 * 2 >= B_DIM * T_DIM) return;

    float4 acc = make_float4(0.f, 0.f, 0.f, 0.f);
    #pragma unroll
    for (int cs = 0; cs < C_SPLIT; cs++) {
        // g_part layout: [cs][b*T + t]; pairs of float2 are contiguous
        const float4 v = ((const float4*)g_part)[(size_t)cs * (B_DIM * T_DIM / 2) + i2];
        acc.x += v.x; acc.y += v.y; acc.z += v.z; acc.w += v.w;
    }
    ((float4*)g_colsum)[i2] = acc;
}

// ---------------- K2b: per-batch scan -> (mean, inv_std) ----------------
#define SCAN_TPB 1024
#define EPT 16                                        // 1024*16 >= 16000

__global__ __launch_bounds__(SCAN_TPB) void scan_kernel()
{
    __shared__ float swS[32], swP[32];

    const int b    = blockIdx.x;
    const int tid  = threadIdx.x;
    const int lane = tid & 31;
    const int wid  = tid >> 5;
    const size_t base = (size_t)b * T_DIM;
    const int start = tid * EPT;

    float vs[EPT], vp[EPT];
    #pragma unroll
    for (int j = 0; j < EPT; j++) {
        const int i = start + j;
        float2 v = (i < T_DIM) ? g_colsum[base + i] : make_float2(0.f, 0.f);
        vs[j] = v.x; vp[j] = v.y;
    }
    #pragma unroll
    for (int j = 1; j < EPT; j++) { vs[j] += vs[j - 1]; vp[j] += vp[j - 1]; }

    float tS = vs[EPT - 1], tP = vp[EPT - 1];
    float iS = tS, iP = tP;
    #pragma unroll
    for (int off = 1; off < 32; off <<= 1) {
        float nS = __shfl_up_sync(0xffffffffu, iS, off);
        float nP = __shfl_up_sync(0xffffffffu, iP, off);
        if (lane >= off) { iS += nS; iP += nP; }
    }
    if (lane == 31) { swS[wid] = iS; swP[wid] = iP; }
    __syncthreads();
    if (wid == 0) {
        float wS = swS[lane], wP = swP[lane];
        #pragma unroll
        for (int off = 1; off < 32; off <<= 1) {
            float nS = __shfl_up_sync(0xffffffffu, wS, off);
            float nP = __shfl_up_sync(0xffffffffu, wP, off);
            if (lane >= off) { wS += nS; wP += nP; }
        }
        swS[lane] = wS - swS[lane];               // exclusive warp offset
        swP[lane] = wP - swP[lane];
    }
    __syncthreads();
    const float excS = swS[wid] + (iS - tS);
    const float excP = swP[wid] + (iP - tP);

    #pragma unroll
    for (int j = 0; j < EPT; j++) {
        const int i = start + j;
        if (i < T_DIM) {
            const float cumS = excS + vs[j];
            const float cumP = excP + vp[j];
            const float cnt  = (float)(i + 1) * (float)C_DIM;
            const float mean = cumS / cnt;
            const float inv  = rsqrtf(cumP / cnt - mean * mean + EPS);
            g_stats[base + i] = make_float2(mean, inv);
        }
    }
}

// ---------------- K3: normalize; stats in registers, channels looped ----------------
__global__ __launch_bounds__(TPB) void norm_kernel(
    const float* __restrict__ x,
    const float* __restrict__ gain,
    const float* __restrict__ bias,
    float* __restrict__ out)
{
    const int cs = blockIdx.y;          // channel slice 0..3
    const int b  = blockIdx.z;
    const int t4 = blockIdx.x * T_PER_BLK + threadIdx.x * 4;
    if (t4 >= T_DIM) return;

    // per-thread stats: loaded ONCE, reused across all 64 channels
    const float4* sp = (const float4*)(g_stats + (size_t)b * T_DIM + t4);
    const float4 s01 = sp[0];           // {mean0, inv0, mean1, inv1}
    const float4 s23 = sp[1];

    const int c0 = cs * K3_CPS;
    const size_t base = ((size_t)b * C_DIM + c0) * T_DIM + t4;
    const float* px = x   + base;
    float*       po = out + base;

    #pragma unroll 8
    for (int c = 0; c < K3_CPS; c++) {
        const float g  = __ldg(gain + c0 + c);
        const float bi = __ldg(bias + c0 + c);
        const float4 v = __ldcs((const float4*)(px + (size_t)c * T_DIM));
        float4 o;
        o.x = fmaf((v.x - s01.x) * s01.y, g, bi);
        o.y = fmaf((v.y - s01.z) * s01.w, g, bi);
        o.z = fmaf((v.z - s23.x) * s23.y, g, bi);
        o.w = fmaf((v.w - s23.z) * s23.w, g, bi);
        __stcs((float4*)(po + (size_t)c * T_DIM), o);
    }
}

extern "C" void kernel_launch(void* const* d_in, const int* in_sizes, int n_in,
                              void* d_out, int out_size)
{
    const float* x    = (const float*)d_in[0];
    const float* gain = (const float*)d_in[1];
    const float* bias = (const float*)d_in[2];
    float* out = (float*)d_out;

    colsum_kernel<<<dim3(NCHUNK, C_SPLIT, B_DIM), TPB>>>(x);
    combine_kernel<<<(B_DIM * T_DIM / 2 + TPB - 1) / TPB, TPB>>>();
    scan_kernel  <<<B_DIM, SCAN_TPB>>>();
    norm_kernel  <<<dim3(NCHUNK, K3_CSPLIT, B_DIM), TPB>>>(x, gain, bias, out);
}